// round 15
// baseline (speedup 1.0000x reference)
#include <cuda_runtime.h>
#include <stdint.h>

// Problem shape is fixed: 32 images, 512x512, 1 channel, float32.
#define NIMG 32
#define H    512
#define WPX  512
#define WPR  16                       // 32-bit words per row (512/32)
#define NSEG 9                        // row-segments per image (grid = 288)
#define SEGR 57                       // nominal output rows per CTA (last: 56)
#define GHOST 16                      // ghost rows each side (= substep count)
#define EROWS (SEGR + 2 * GHOST)      // 89 extended rows held in smem
#define TPB 384                       // 12 warps; rows r = tid>>2 (r<89 live)
#define NWARPS (TPB / 32)

__device__ __forceinline__ uint32_t maj3(uint32_t a, uint32_t b, uint32_t c) {
    return (a & b) | (c & (a | b));    // 1 LOP3
}

// Pairwise sync with vertically adjacent warps only (named barriers, 64 thr).
// A 2-warp barrier cannot skew more than one substep (32 arrivals < 64).
__device__ __forceinline__ void pairsync(int warp) {
    if (warp > 0)
        asm volatile("bar.sync %0, %1;" :: "r"(warp), "r"(64) : "memory");
    if (warp < NWARPS - 1)
        asm volatile("bar.sync %0, %1;" :: "r"(warp + 1), "r"(64) : "memory");
}

// Zhang-Suen DELETE mask for one 32-pixel word, given the 8 neighbor masks.
// acnt==1 computed as acnt<=1 (valid since 2<=bcnt<=6 implies acnt>=1).
template<bool FIRST>
__device__ __forceinline__ uint32_t word_delete(
    uint32_t mi, uint32_t P2, uint32_t P3, uint32_t P4, uint32_t P5,
    uint32_t P6, uint32_t P7, uint32_t P8, uint32_t P9)
{
    // ---- bcnt via CSA: need 2 <= bcnt <= 6 ----
    uint32_t sa = P2 ^ P3 ^ P4, ca = maj3(P2, P3, P4);
    uint32_t sb = P5 ^ P6 ^ P7, cb = maj3(P5, P6, P7);
    uint32_t sc = P8 ^ P9,      cc = P8 & P9;
    uint32_t S0s = sa ^ sb ^ sc, C1 = maj3(sa, sb, sc);
    uint32_t S1s = ca ^ cb ^ cc, C2 = maj3(ca, cb, cc);
    uint32_t ge2 = C1 | S1s | C2;
    uint32_t ge7 = C2 & maj3(C1, S1s, S0s);

    // ---- acnt <= 1: all carries of the transition CSA are zero ----
    uint32_t t0 = ~P2 & P3, t1 = ~P3 & P4, t2 = ~P4 & P5, t3 = ~P5 & P6;
    uint32_t t4 = ~P6 & P7, t5 = ~P7 & P8, t6 = ~P8 & P9, t7 = ~P9 & P2;
    uint32_t aca = maj3(t0, t1, t2);
    uint32_t acb = maj3(t3, t4, t5);
    uint32_t acc = t6 & t7;
    uint32_t asa = t0 ^ t1 ^ t2;
    uint32_t asb = t3 ^ t4 ^ t5;
    uint32_t asc = t6 ^ t7;
    uint32_t A1  = maj3(asa, asb, asc);
    uint32_t ex1 = ~(A1 | aca | acb) & ~acc;

    // ---- c1 & c2 ----
    uint32_t inner;
    if (FIRST) inner = (P4 & P6) & (P2 | P8);
    else       inner = (P2 & P8) & (P4 | P6);

    return mi & ge2 & ~ge7 & ex1 & ~inner;
}

// Compute 4 output words (quarter q of smem row r) with the middle row
// CARRIED IN REGISTERS m[4] (this thread's own output from the previous
// substep; buffers are still fully written, so neighbor halo words ml/mr
// come from smem as before). Updates m[] to the new output.
// Returns OR of all delete bits. Caller guarantees 1 <= r <= EROWS-2.
template<bool FIRST>
__device__ __forceinline__ uint32_t strip4c(
    const uint32_t* __restrict__ S, uint32_t* __restrict__ D, int r, int q,
    uint32_t* __restrict__ m)
{
    int base = r * WPR + q * 4;

    uint4 u4 = *(const uint4*)&S[base - WPR];
    uint4 d4 = *(const uint4*)&S[base + WPR];
    uint32_t ml = q ? S[base - 1]       : 0u, mr = (q < 3) ? S[base + 4]       : 0u;
    uint32_t ul = q ? S[base - WPR - 1] : 0u, ur = (q < 3) ? S[base - WPR + 4] : 0u;
    uint32_t dl = q ? S[base + WPR - 1] : 0u, dr = (q < 3) ? S[base + WPR + 4] : 0u;

    uint32_t u[4] = {u4.x, u4.y, u4.z, u4.w};
    uint32_t d[4] = {d4.x, d4.y, d4.z, d4.w};
    uint32_t o[4];
    uint32_t dacc = 0;

    #pragma unroll
    for (int j = 0; j < 4; ++j) {
        uint32_t up = u[j], mi = m[j], dn = d[j];
        uint32_t upl = j ? u[j - 1] : ul, upr = (j < 3) ? u[j + 1] : ur;
        uint32_t mil = j ? m[j - 1] : ml, mir = (j < 3) ? m[j + 1] : mr;
        uint32_t dnl = j ? d[j - 1] : dl, dnr = (j < 3) ? d[j + 1] : dr;

        uint32_t P2 = up;
        uint32_t P3 = __funnelshift_r(up, upr, 1);
        uint32_t P4 = __funnelshift_r(mi, mir, 1);
        uint32_t P5 = __funnelshift_r(dn, dnr, 1);
        uint32_t P6 = dn;
        uint32_t P7 = __funnelshift_l(dnl, dn, 1);
        uint32_t P8 = __funnelshift_l(mil, mi, 1);
        uint32_t P9 = __funnelshift_l(upl, up, 1);

        uint32_t del = word_delete<FIRST>(mi, P2, P3, P4, P5, P6, P7, P8, P9);
        dacc |= del;
        o[j] = mi & ~del;
    }

    *(uint4*)&D[base] = make_uint4(o[0], o[1], o[2], o[3]);
    m[0] = o[0]; m[1] = o[1]; m[2] = o[2]; m[3] = o[3];
    return dacc;
}

// ---------------------------------------------------------------------------
// Fully fused kernel (pack -> up to 16 substeps -> unpack), 288 CTAs
// (32 images x 9 segments of 57 rows; last segment 56, masked). All 288 fit
// resident (148 SMs x 2), 140 SMs carry 2 CTAs -> better balance than 256.
// Pairwise warp sync on odd substeps, CTA sync + global convergence check on
// even substeps. Middle row carried in registers across substeps (window
// shrinks, so active@k+1 implies active@k and the carry is always fresh).
// Shrinking window [k, 88-k] holds exactly the rows exact at substep k.
// ---------------------------------------------------------------------------
__global__ void __launch_bounds__(TPB, 2)
fused_skeleton_kernel(const float* __restrict__ in, float* __restrict__ out) {
    __shared__ uint32_t S0[EROWS * WPR];
    __shared__ uint32_t S1[EROWS * WPR];
    __shared__ int sflags[17];
    __shared__ float4 LUT[16];          // nibble -> 4 floats (0.0/1.0)

    int tid  = threadIdx.x;
    int warp = tid >> 5;
    int lane = tid & 31;
    int img  = blockIdx.x / NSEG;
    int seg  = blockIdx.x - img * NSEG;
    int segrow0 = seg * SEGR - GHOST;               // global row of ext row 0

    if (tid < 17) sflags[tid] = 0;
    if (tid < 16)
        LUT[tid] = make_float4((float)(tid & 1), (float)((tid >> 1) & 1),
                               (float)((tid >> 2) & 1), (float)((tid >> 3) & 1));

    // ---- Pack phase: warp w ballots its extended rows 8w..8w+7 (<89) ----
    {
        #pragma unroll 1
        for (int rr = 0; rr < 8; ++rr) {
            int r = warp * 8 + rr;                  // extended row
            if (r >= EROWS) break;
            int grow = segrow0 + r;
            bool valid = (grow >= 0) && (grow < H);
            const float* p = in + ((size_t)img * H + (valid ? grow : 0)) * WPX + lane;
            float v[16];
            #pragma unroll
            for (int i = 0; i < 16; ++i)            // MLP = 16
                v[i] = valid ? p[i * 32] : 0.0f;
            #pragma unroll
            for (int i = 0; i < 16; ++i) {
                uint32_t b = __ballot_sync(0xffffffffu, v[i] >= 0.5f);
                if (lane == 0) S0[r * WPR + i] = b;
            }
        }
    }
    __syncthreads();    // orders pack stores + LUT/flag init CTA-wide

    // ---- up to 16 substeps, shrinking window, early convergence exit ----
    int r = tid >> 2;                 // extended row (warp w: 8w..8w+7)
    int q = tid & 3;                  // quarter-row

    uint32_t mreg[4] = {0u, 0u, 0u, 0u};            // carried middle row
    if (r < EROWS) *(uint4*)mreg = *(const uint4*)&S0[r * WPR + q * 4];

    #pragma unroll 1
    for (int k = 1; k <= 16; ++k) {
        bool active = (r >= k) && (r <= EROWS - 1 - k);
        uint32_t dOR = 0;
        if (k & 1) { if (active) dOR = strip4c<true >(S0, S1, r, q, mreg); }
        else       { if (active) dOR = strip4c<false>(S1, S0, r, q, mreg); }

        unsigned anym = __ballot_sync(0xffffffffu, dOR != 0u);
        if (anym && lane == 0) sflags[k] = 1;       // benign same-value race

        if (k & 1) {
            pairsync(warp);
        } else {
            __syncthreads();                        // flags + data visible
            if (sflags[k - 1] == 0 && sflags[k] == 0) break;   // fixed point
        }
    }
    // Loop exits only at even k: final state in S0; exact rows 16..72.

    // ---- Unpack phase: warps 2..9 write their own rows via the LUT ----
    if (warp >= 2 && warp <= 9) {
        #pragma unroll
        for (int rr = 0; rr < 8; ++rr) {
            int row  = warp * 8 + rr;               // extended row 16..79
            int orow = seg * SEGR + (row - GHOST);  // global output row
            if (row < GHOST + SEGR && orow < H) {
                float4* o4 = (float4*)(out + ((size_t)img * H + orow) * WPX);
                int sh = (lane & 7) * 4;
                #pragma unroll
                for (int j = 0; j < 4; ++j) {       // 512B contiguous per STG
                    uint32_t w = S0[row * WPR + j * 4 + (lane >> 3)];
                    o4[j * 32 + lane] = LUT[(w >> sh) & 0xFu];
                }
            }
        }
    }
}

extern "C" void kernel_launch(void* const* d_in, const int* in_sizes, int n_in,
                              void* d_out, int out_size) {
    (void)in_sizes; (void)n_in; (void)out_size;
    const float* in = (const float*)d_in[0];
    float* out = (float*)d_out;

    fused_skeleton_kernel<<<NIMG * NSEG, TPB>>>(in, out);
}

// round 16
// speedup vs baseline: 1.0708x; 1.0708x over previous
#include <cuda_runtime.h>
#include <stdint.h>

// Problem shape is fixed: 32 images, 512x512, 1 channel, float32.
#define NIMG 32
#define H    512
#define WPX  512
#define WPR  16                       // 32-bit words per row (512/32)
#define NSEG 9                        // row-segments per image (grid = 288)
#define SEGR 57                       // nominal output rows per CTA (last: 56)
#define GHOST 16                      // ghost rows each side (= substep count)
#define EROWS (SEGR + 2 * GHOST)      // 89 extended rows held in smem
#define TPB 384                       // 12 warps; rows r = tid>>2 (r<89 live)
#define NWARPS (TPB / 32)

__device__ __forceinline__ uint32_t maj3(uint32_t a, uint32_t b, uint32_t c) {
    return (a & b) | (c & (a | b));    // 1 LOP3
}

// One-wait pairwise sync: warp w arrives (non-blocking) at both neighbors'
// gates, then blocks on its OWN gate only. Gate of warp w = named barrier
// id w+1 (id 0 is reserved for __syncthreads); participants: warp w (sync)
// + neighbors (arrive). Counts: interior 96, edge 64. Warp w passes its gate
// only after both neighbors finished the current substep -> skew <= 1
// substep, exactly as the old two-bar.sync version.
__device__ __forceinline__ void gate_sync(int warp) {
    if (warp > 0) {                     // arrive at warp-1's gate (id = warp)
        int cnt = (warp - 1 == 0 || warp - 1 == NWARPS - 1) ? 64 : 96;
        asm volatile("bar.arrive %0, %1;" :: "r"(warp), "r"(cnt) : "memory");
    }
    if (warp < NWARPS - 1) {            // arrive at warp+1's gate (id = warp+2)
        int cnt = (warp + 1 == NWARPS - 1) ? 64 : 96;
        asm volatile("bar.arrive %0, %1;" :: "r"(warp + 2), "r"(cnt) : "memory");
    }
    int cnt = (warp == 0 || warp == NWARPS - 1) ? 64 : 96;
    asm volatile("bar.sync %0, %1;" :: "r"(warp + 1), "r"(cnt) : "memory");
}

// Zhang-Suen DELETE mask for one 32-pixel word, given the 8 neighbor masks.
// acnt==1 computed as acnt<=1 (valid since 2<=bcnt<=6 implies acnt>=1).
template<bool FIRST>
__device__ __forceinline__ uint32_t word_delete(
    uint32_t mi, uint32_t P2, uint32_t P3, uint32_t P4, uint32_t P5,
    uint32_t P6, uint32_t P7, uint32_t P8, uint32_t P9)
{
    // ---- bcnt via CSA: need 2 <= bcnt <= 6 ----
    uint32_t sa = P2 ^ P3 ^ P4, ca = maj3(P2, P3, P4);
    uint32_t sb = P5 ^ P6 ^ P7, cb = maj3(P5, P6, P7);
    uint32_t sc = P8 ^ P9,      cc = P8 & P9;
    uint32_t S0s = sa ^ sb ^ sc, C1 = maj3(sa, sb, sc);
    uint32_t S1s = ca ^ cb ^ cc, C2 = maj3(ca, cb, cc);
    uint32_t ge2 = C1 | S1s | C2;
    uint32_t ge7 = C2 & maj3(C1, S1s, S0s);

    // ---- acnt <= 1: all carries of the transition CSA are zero ----
    uint32_t t0 = ~P2 & P3, t1 = ~P3 & P4, t2 = ~P4 & P5, t3 = ~P5 & P6;
    uint32_t t4 = ~P6 & P7, t5 = ~P7 & P8, t6 = ~P8 & P9, t7 = ~P9 & P2;
    uint32_t aca = maj3(t0, t1, t2);
    uint32_t acb = maj3(t3, t4, t5);
    uint32_t acc = t6 & t7;
    uint32_t asa = t0 ^ t1 ^ t2;
    uint32_t asb = t3 ^ t4 ^ t5;
    uint32_t asc = t6 ^ t7;
    uint32_t A1  = maj3(asa, asb, asc);
    uint32_t ex1 = ~(A1 | aca | acb) & ~acc;

    // ---- c1 & c2 ----
    uint32_t inner;
    if (FIRST) inner = (P4 & P6) & (P2 | P8);
    else       inner = (P2 & P8) & (P4 | P6);

    return mi & ge2 & ~ge7 & ex1 & ~inner;
}

// Compute 4 output words (quarter q of smem row r) with the middle row
// carried in registers m[4] (this thread's own output from the previous
// substep). Updates m[] to the new output. Returns OR of all delete bits.
// Caller guarantees 1 <= r <= EROWS-2.
template<bool FIRST>
__device__ __forceinline__ uint32_t strip4c(
    const uint32_t* __restrict__ S, uint32_t* __restrict__ D, int r, int q,
    uint32_t* __restrict__ m)
{
    int base = r * WPR + q * 4;

    uint4 u4 = *(const uint4*)&S[base - WPR];
    uint4 d4 = *(const uint4*)&S[base + WPR];
    uint32_t ml = q ? S[base - 1]       : 0u, mr = (q < 3) ? S[base + 4]       : 0u;
    uint32_t ul = q ? S[base - WPR - 1] : 0u, ur = (q < 3) ? S[base - WPR + 4] : 0u;
    uint32_t dl = q ? S[base + WPR - 1] : 0u, dr = (q < 3) ? S[base + WPR + 4] : 0u;

    uint32_t u[4] = {u4.x, u4.y, u4.z, u4.w};
    uint32_t d[4] = {d4.x, d4.y, d4.z, d4.w};
    uint32_t o[4];
    uint32_t dacc = 0;

    #pragma unroll
    for (int j = 0; j < 4; ++j) {
        uint32_t up = u[j], mi = m[j], dn = d[j];
        uint32_t upl = j ? u[j - 1] : ul, upr = (j < 3) ? u[j + 1] : ur;
        uint32_t mil = j ? m[j - 1] : ml, mir = (j < 3) ? m[j + 1] : mr;
        uint32_t dnl = j ? d[j - 1] : dl, dnr = (j < 3) ? d[j + 1] : dr;

        uint32_t P2 = up;
        uint32_t P3 = __funnelshift_r(up, upr, 1);
        uint32_t P4 = __funnelshift_r(mi, mir, 1);
        uint32_t P5 = __funnelshift_r(dn, dnr, 1);
        uint32_t P6 = dn;
        uint32_t P7 = __funnelshift_l(dnl, dn, 1);
        uint32_t P8 = __funnelshift_l(mil, mi, 1);
        uint32_t P9 = __funnelshift_l(upl, up, 1);

        uint32_t del = word_delete<FIRST>(mi, P2, P3, P4, P5, P6, P7, P8, P9);
        dacc |= del;
        o[j] = mi & ~del;
    }

    *(uint4*)&D[base] = make_uint4(o[0], o[1], o[2], o[3]);
    m[0] = o[0]; m[1] = o[1]; m[2] = o[2]; m[3] = o[3];
    return dacc;
}

// ---------------------------------------------------------------------------
// Fully fused kernel (pack -> up to 16 substeps -> unpack), 288 CTAs
// (32 images x 9 segments of 57 rows; last 56, masked). One-wait gate_sync
// on odd substeps; CTA sync + per-PAIR convergence check on even substeps.
// Active window clamped both by the shrinking exactness bound [k, 88-k] and
// by the image interior (out-of-image rows are zero forever: never computed;
// both buffers' copies zeroed once at pack so neighbor reads stay correct).
// ---------------------------------------------------------------------------
__global__ void __launch_bounds__(TPB, 2)
fused_skeleton_kernel(const float* __restrict__ in, float* __restrict__ out) {
    __shared__ uint32_t S0[EROWS * WPR];
    __shared__ uint32_t S1[EROWS * WPR];
    __shared__ int sflags[9];           // one per substep pair
    __shared__ float4 LUT[16];          // nibble -> 4 floats (0.0/1.0)

    int tid  = threadIdx.x;
    int warp = tid >> 5;
    int lane = tid & 31;
    int img  = blockIdx.x / NSEG;
    int seg  = blockIdx.x - img * NSEG;
    int segrow0 = seg * SEGR - GHOST;               // global row of ext row 0

    // Image-interior clamp for this CTA (rows outside stay zero forever).
    int lo0 = (segrow0 < 0) ? -segrow0 : 0;
    int hi0 = (H - 1) - segrow0; if (hi0 > EROWS - 1) hi0 = EROWS - 1;

    if (tid < 9) sflags[tid] = 0;
    if (tid < 16)
        LUT[tid] = make_float4((float)(tid & 1), (float)((tid >> 1) & 1),
                               (float)((tid >> 2) & 1), (float)((tid >> 3) & 1));

    // ---- Pack phase: warp w ballots its extended rows 8w..8w+7 (<89) ----
    {
        #pragma unroll 1
        for (int rr = 0; rr < 8; ++rr) {
            int r = warp * 8 + rr;                  // extended row
            if (r >= EROWS) break;
            int grow = segrow0 + r;
            bool valid = (grow >= 0) && (grow < H);
            if (valid) {
                const float* p = in + ((size_t)img * H + grow) * WPX + lane;
                float v[16];
                #pragma unroll
                for (int i = 0; i < 16; ++i)        // MLP = 16
                    v[i] = p[i * 32];
                #pragma unroll
                for (int i = 0; i < 16; ++i) {
                    uint32_t b = __ballot_sync(0xffffffffu, v[i] >= 0.5f);
                    if (lane == 0) S0[r * WPR + i] = b;
                }
            } else if (lane < 16) {
                // Out-of-image rows: zero in BOTH buffers, once. Never
                // recomputed (clamped out of the window), read by neighbors.
                S0[r * WPR + lane] = 0u;
                S1[r * WPR + lane] = 0u;
            }
        }
    }
    __syncthreads();    // orders pack stores + LUT/flag init CTA-wide

    // ---- up to 16 substeps, shrinking+clamped window, pair-wise exit ----
    int r = tid >> 2;                 // extended row (warp w: 8w..8w+7)
    int q = tid & 3;                  // quarter-row

    uint32_t mreg[4] = {0u, 0u, 0u, 0u};            // carried middle row
    if (r < EROWS) *(uint4*)mreg = *(const uint4*)&S0[r * WPR + q * 4];

    uint32_t dpair = 0;
    #pragma unroll 1
    for (int k = 1; k <= 16; ++k) {
        int lo = (k > lo0) ? k : lo0;
        int hi = EROWS - 1 - k; if (hi > hi0) hi = hi0;
        bool active = (r >= lo) && (r <= hi);

        if (k & 1) {
            if (active) dpair = strip4c<true >(S0, S1, r, q, mreg);
            else        dpair = 0;
            gate_sync(warp);
        } else {
            if (active) dpair |= strip4c<false>(S1, S0, r, q, mreg);
            unsigned anym = __ballot_sync(0xffffffffu, dpair != 0u);
            if (anym && lane == 0) sflags[k >> 1] = 1;  // benign dup write
            __syncthreads();                        // flags + data visible
            if (sflags[k >> 1] == 0) break;         // quiet pair: fixed point
        }
    }
    // Loop exits only at even k: final state in S0; exact rows 16..16+SEGR-1.

    // ---- Unpack phase: warps 2..9 write their own rows via the LUT ----
    if (warp >= 2 && warp <= 9) {
        #pragma unroll
        for (int rr = 0; rr < 8; ++rr) {
            int row  = warp * 8 + rr;               // extended row 16..79
            int orow = seg * SEGR + (row - GHOST);  // global output row
            if (row < GHOST + SEGR && orow < H) {
                float4* o4 = (float4*)(out + ((size_t)img * H + orow) * WPX);
                int sh = (lane & 7) * 4;
                #pragma unroll
                for (int j = 0; j < 4; ++j) {       // 512B contiguous per STG
                    uint32_t w = S0[row * WPR + j * 4 + (lane >> 3)];
                    o4[j * 32 + lane] = LUT[(w >> sh) & 0xFu];
                }
            }
        }
    }
}

extern "C" void kernel_launch(void* const* d_in, const int* in_sizes, int n_in,
                              void* d_out, int out_size) {
    (void)in_sizes; (void)n_in; (void)out_size;
    const float* in = (const float*)d_in[0];
    float* out = (float*)d_out;

    fused_skeleton_kernel<<<NIMG * NSEG, TPB>>>(in, out);
}

// round 17
// speedup vs baseline: 1.0972x; 1.0246x over previous
#include <cuda_runtime.h>
#include <stdint.h>

// Problem shape is fixed: 32 images, 512x512, 1 channel, float32.
#define NIMG 32
#define H    512
#define WPX  512
#define WPR  16                       // 32-bit words per row (512/32)
#define NSEG 9                        // row-segments per image (grid = 288)
#define SEGR 57                       // nominal output rows per CTA (last: 56)
#define GHOST 16                      // ghost rows each side (= substep count)
#define EROWS (SEGR + 2 * GHOST)      // 89 extended rows held in smem
#define TPB 384                       // 12 warps; rows r = tid>>2 (r<89 live)
#define NWARPS (TPB / 32)

__device__ __forceinline__ uint32_t maj3(uint32_t a, uint32_t b, uint32_t c) {
    return (a & b) | (c & (a | b));    // 1 LOP3
}

// One-wait pairwise sync: warp w arrives (non-blocking) at both neighbors'
// gates, then blocks on its OWN gate only. Gate of warp w = named barrier
// id w+1 (id 0 is reserved for __syncthreads); participants: warp w (sync)
// + neighbors (arrive). Counts: interior 96, edge 64. Warp w passes its gate
// only after both neighbors finished the current substep -> skew <= 1
// substep, exactly as a two-bar.sync version.
__device__ __forceinline__ void gate_sync(int warp) {
    if (warp > 0) {                     // arrive at warp-1's gate (id = warp)
        int cnt = (warp - 1 == 0 || warp - 1 == NWARPS - 1) ? 64 : 96;
        asm volatile("bar.arrive %0, %1;" :: "r"(warp), "r"(cnt) : "memory");
    }
    if (warp < NWARPS - 1) {            // arrive at warp+1's gate (id = warp+2)
        int cnt = (warp + 1 == NWARPS - 1) ? 64 : 96;
        asm volatile("bar.arrive %0, %1;" :: "r"(warp + 2), "r"(cnt) : "memory");
    }
    int cnt = (warp == 0 || warp == NWARPS - 1) ? 64 : 96;
    asm volatile("bar.sync %0, %1;" :: "r"(warp + 1), "r"(cnt) : "memory");
}

// Zhang-Suen DELETE mask for one 32-pixel word, given the 8 neighbor masks.
// acnt==1 computed as acnt<=1 (valid since 2<=bcnt<=6 implies acnt>=1).
template<bool FIRST>
__device__ __forceinline__ uint32_t word_delete(
    uint32_t mi, uint32_t P2, uint32_t P3, uint32_t P4, uint32_t P5,
    uint32_t P6, uint32_t P7, uint32_t P8, uint32_t P9)
{
    // ---- bcnt via CSA: need 2 <= bcnt <= 6 ----
    uint32_t sa = P2 ^ P3 ^ P4, ca = maj3(P2, P3, P4);
    uint32_t sb = P5 ^ P6 ^ P7, cb = maj3(P5, P6, P7);
    uint32_t sc = P8 ^ P9,      cc = P8 & P9;
    uint32_t S0s = sa ^ sb ^ sc, C1 = maj3(sa, sb, sc);
    uint32_t S1s = ca ^ cb ^ cc, C2 = maj3(ca, cb, cc);
    uint32_t ge2 = C1 | S1s | C2;
    uint32_t ge7 = C2 & maj3(C1, S1s, S0s);

    // ---- acnt <= 1: all carries of the transition CSA are zero ----
    uint32_t t0 = ~P2 & P3, t1 = ~P3 & P4, t2 = ~P4 & P5, t3 = ~P5 & P6;
    uint32_t t4 = ~P6 & P7, t5 = ~P7 & P8, t6 = ~P8 & P9, t7 = ~P9 & P2;
    uint32_t aca = maj3(t0, t1, t2);
    uint32_t acb = maj3(t3, t4, t5);
    uint32_t acc = t6 & t7;
    uint32_t asa = t0 ^ t1 ^ t2;
    uint32_t asb = t3 ^ t4 ^ t5;
    uint32_t asc = t6 ^ t7;
    uint32_t A1  = maj3(asa, asb, asc);
    uint32_t ex1 = ~(A1 | aca | acb) & ~acc;

    // ---- c1 & c2 ----
    uint32_t inner;
    if (FIRST) inner = (P4 & P6) & (P2 | P8);
    else       inner = (P2 & P8) & (P4 | P6);

    return mi & ge2 & ~ge7 & ex1 & ~inner;
}

// Compute 4 output words (quarter q of smem row r) with the middle row
// carried in registers m[4] (this thread's own output from the previous
// substep). Updates m[] to the new output. Returns OR of all delete bits.
// Caller guarantees 1 <= r <= EROWS-2.
template<bool FIRST>
__device__ __forceinline__ uint32_t strip4c(
    const uint32_t* __restrict__ S, uint32_t* __restrict__ D, int r, int q,
    uint32_t* __restrict__ m)
{
    int base = r * WPR + q * 4;

    uint4 u4 = *(const uint4*)&S[base - WPR];
    uint4 d4 = *(const uint4*)&S[base + WPR];
    uint32_t ml = q ? S[base - 1]       : 0u, mr = (q < 3) ? S[base + 4]       : 0u;
    uint32_t ul = q ? S[base - WPR - 1] : 0u, ur = (q < 3) ? S[base - WPR + 4] : 0u;
    uint32_t dl = q ? S[base + WPR - 1] : 0u, dr = (q < 3) ? S[base + WPR + 4] : 0u;

    uint32_t u[4] = {u4.x, u4.y, u4.z, u4.w};
    uint32_t d[4] = {d4.x, d4.y, d4.z, d4.w};
    uint32_t o[4];
    uint32_t dacc = 0;

    #pragma unroll
    for (int j = 0; j < 4; ++j) {
        uint32_t up = u[j], mi = m[j], dn = d[j];
        uint32_t upl = j ? u[j - 1] : ul, upr = (j < 3) ? u[j + 1] : ur;
        uint32_t mil = j ? m[j - 1] : ml, mir = (j < 3) ? m[j + 1] : mr;
        uint32_t dnl = j ? d[j - 1] : dl, dnr = (j < 3) ? d[j + 1] : dr;

        uint32_t P2 = up;
        uint32_t P3 = __funnelshift_r(up, upr, 1);
        uint32_t P4 = __funnelshift_r(mi, mir, 1);
        uint32_t P5 = __funnelshift_r(dn, dnr, 1);
        uint32_t P6 = dn;
        uint32_t P7 = __funnelshift_l(dnl, dn, 1);
        uint32_t P8 = __funnelshift_l(mil, mi, 1);
        uint32_t P9 = __funnelshift_l(upl, up, 1);

        uint32_t del = word_delete<FIRST>(mi, P2, P3, P4, P5, P6, P7, P8, P9);
        dacc |= del;
        o[j] = mi & ~del;
    }

    *(uint4*)&D[base] = make_uint4(o[0], o[1], o[2], o[3]);
    m[0] = o[0]; m[1] = o[1]; m[2] = o[2]; m[3] = o[3];
    return dacc;
}

// ---------------------------------------------------------------------------
// Fully fused kernel (pack -> up to 16 substeps -> unpack), 288 CTAs
// (32 images x 9 segments of 57 rows; last 56, masked). One-wait gate_sync
// on odd substeps; CTA sync + per-PAIR convergence check on even substeps.
// Active window clamped by the shrinking exactness bound [k, 88-k] AND the
// image interior (out-of-image rows zero forever; zeroed once in BOTH
// buffers at pack so neighbor reads stay correct). Unpack is flat-indexed
// across ALL 12 warps (loop always exits through __syncthreads at even k,
// so S0 is CTA-visible) with streaming (evict-first) stores.
// ---------------------------------------------------------------------------
__global__ void __launch_bounds__(TPB, 2)
fused_skeleton_kernel(const float* __restrict__ in, float* __restrict__ out) {
    __shared__ uint32_t S0[EROWS * WPR];
    __shared__ uint32_t S1[EROWS * WPR];
    __shared__ int sflags[9];           // one per substep pair
    __shared__ float4 LUT[16];          // nibble -> 4 floats (0.0/1.0)

    int tid  = threadIdx.x;
    int warp = tid >> 5;
    int lane = tid & 31;
    int img  = blockIdx.x / NSEG;
    int seg  = blockIdx.x - img * NSEG;
    int segrow0 = seg * SEGR - GHOST;               // global row of ext row 0

    // Image-interior clamp for this CTA (rows outside stay zero forever).
    int lo0 = (segrow0 < 0) ? -segrow0 : 0;
    int hi0 = (H - 1) - segrow0; if (hi0 > EROWS - 1) hi0 = EROWS - 1;

    if (tid < 9) sflags[tid] = 0;
    if (tid < 16)
        LUT[tid] = make_float4((float)(tid & 1), (float)((tid >> 1) & 1),
                               (float)((tid >> 2) & 1), (float)((tid >> 3) & 1));

    // ---- Pack phase: warp w ballots its extended rows 8w..8w+7 (<89) ----
    {
        #pragma unroll 1
        for (int rr = 0; rr < 8; ++rr) {
            int r = warp * 8 + rr;                  // extended row
            if (r >= EROWS) break;
            int grow = segrow0 + r;
            bool valid = (grow >= 0) && (grow < H);
            if (valid) {
                const float* p = in + ((size_t)img * H + grow) * WPX + lane;
                float v[16];
                #pragma unroll
                for (int i = 0; i < 16; ++i)        // MLP = 16
                    v[i] = p[i * 32];
                #pragma unroll
                for (int i = 0; i < 16; ++i) {
                    uint32_t b = __ballot_sync(0xffffffffu, v[i] >= 0.5f);
                    if (lane == 0) S0[r * WPR + i] = b;
                }
            } else if (lane < 16) {
                // Out-of-image rows: zero in BOTH buffers, once. Never
                // recomputed (clamped out of the window), read by neighbors.
                S0[r * WPR + lane] = 0u;
                S1[r * WPR + lane] = 0u;
            }
        }
    }
    __syncthreads();    // orders pack stores + LUT/flag init CTA-wide

    // ---- up to 16 substeps, shrinking+clamped window, pair-wise exit ----
    int r = tid >> 2;                 // extended row (warp w: 8w..8w+7)
    int q = tid & 3;                  // quarter-row

    uint32_t mreg[4] = {0u, 0u, 0u, 0u};            // carried middle row
    if (r < EROWS) *(uint4*)mreg = *(const uint4*)&S0[r * WPR + q * 4];

    uint32_t dpair = 0;
    #pragma unroll 1
    for (int k = 1; k <= 16; ++k) {
        int lo = (k > lo0) ? k : lo0;
        int hi = EROWS - 1 - k; if (hi > hi0) hi = hi0;
        bool active = (r >= lo) && (r <= hi);

        if (k & 1) {
            if (active) dpair = strip4c<true >(S0, S1, r, q, mreg);
            else        dpair = 0;
            gate_sync(warp);
        } else {
            if (active) dpair |= strip4c<false>(S1, S0, r, q, mreg);
            unsigned anym = __ballot_sync(0xffffffffu, dpair != 0u);
            if (anym && lane == 0) sflags[k >> 1] = 1;  // benign dup write
            __syncthreads();                        // flags + data visible
            if (sflags[k >> 1] == 0) break;         // quiet pair: fixed point
        }
    }
    // Loop exits only at even k, right after __syncthreads: S0 final and
    // CTA-visible; exact rows are GHOST..GHOST+SEGR-1 (clipped to image).

    // ---- Unpack phase: flat-indexed over ALL warps, streaming stores ----
    {
        int nrows = H - seg * SEGR; if (nrows > SEGR) nrows = SEGR;   // 57/56
        float4* o4 = (float4*)(out + ((size_t)img * H + seg * SEGR) * WPX);
        int total = nrows * 128;                    // float4 per segment
        #pragma unroll 2
        for (int idx = tid; idx < total; idx += TPB) {
            int row  = idx >> 7;                    // 128 float4 per row
            int word = (idx & 127) >> 3;            // 8 float4 per word
            uint32_t w = S0[(row + GHOST) * WPR + word];
            int sh = (idx & 7) * 4;
            __stcs(&o4[idx], LUT[(w >> sh) & 0xFu]);
        }
    }
}

extern "C" void kernel_launch(void* const* d_in, const int* in_sizes, int n_in,
                              void* d_out, int out_size) {
    (void)in_sizes; (void)n_in; (void)out_size;
    const float* in = (const float*)d_in[0];
    float* out = (float*)d_out;

    fused_skeleton_kernel<<<NIMG * NSEG, TPB>>>(in, out);
}